// round 1
// baseline (speedup 1.0000x reference)
#include <cuda_runtime.h>

#define NS      16384      // samples (16*32*32)
#define DD      128        // embed dim
#define KK      10000      // clusters
#define KPAD    10112      // 79 * 128
#define KT      128        // k-tile width
#define NKT     79
#define TM      128        // samples per block
#define NTHREADS 256
#define XS_STRIDE 130      // padded (even, conflict-free broadcast reads)

#define SMEM_BYTES ((DD * XS_STRIDE + DD * KT + KT) * 4)

__device__ float g_h[KPAD];       // 0.5 * ||m_k||^2, padded with -inf
__device__ int   g_idx[NS];
__device__ float g_partial[512];

// ---------------------------------------------------------------------------
// Kernel 1: h_k = 0.5 * sum_d m[d][k]^2   (padded entries -> -inf)
// ---------------------------------------------------------------------------
__global__ void h_kernel(const float* __restrict__ cm) {
    int k = blockIdx.x * blockDim.x + threadIdx.x;
    if (k >= KPAD) return;
    if (k < KK) {
        float s = 0.f;
#pragma unroll 8
        for (int d = 0; d < DD; d++) {
            float v = cm[(size_t)d * KK + k];
            s = fmaf(v, v, s);
        }
        g_h[k] = 0.5f * s;
    } else {
        g_h[k] = -3.0e38f;
    }
}

// ---------------------------------------------------------------------------
// Kernel 2: fused GEMM + running argmax.
// Block: 256 threads, TM=128 samples, loops over all K in KT=128 tiles.
// Thread (tx = tid&15, ty = tid>>4): 8 samples (ty*8..+7, packed in f32x2
// pairs) x 8 clusters (tx*8..+7). Inner product via fma.rn.f32x2 (FFMA2) --
// required for full fp32 rate on sm_103a.
// ---------------------------------------------------------------------------
extern __shared__ float smem_dyn[];

__global__ void __launch_bounds__(NTHREADS, 1)
argmax_kernel(const float* __restrict__ x, const float* __restrict__ cm,
              float* __restrict__ out_idx) {
    float* xs = smem_dyn;                     // [DD][XS_STRIDE]  (x transposed)
    float* ms = smem_dyn + DD * XS_STRIDE;    // [DD][KT]
    float* hs = ms + DD * KT;                 // [KT]

    const int tid = threadIdx.x;
    const int tx = tid & 15;
    const int ty = tid >> 4;
    const int n0 = blockIdx.x * TM;

    // --- load + transpose x tile: xs[d][s] ---
    const float4* xg = reinterpret_cast<const float4*>(x + (size_t)n0 * DD);
    for (int f = tid; f < TM * DD / 4; f += NTHREADS) {
        float4 v = xg[f];
        int s = f >> 5;            // f / (DD/4)
        int d = (f & 31) << 2;
        xs[(d + 0) * XS_STRIDE + s] = v.x;
        xs[(d + 1) * XS_STRIDE + s] = v.y;
        xs[(d + 2) * XS_STRIDE + s] = v.z;
        xs[(d + 3) * XS_STRIDE + s] = v.w;
    }

    float best[8];
    int   bidx[8];
#pragma unroll
    for (int i = 0; i < 8; i++) { best[i] = -3.4e38f; bidx[i] = 0; }

    const float* xrow = xs + ty * 8;
    const float* mrow = ms + tx * 8;

    for (int t = 0; t < NKT; t++) {
        const int k0 = t * KT;
        __syncthreads();   // previous tile's compute done before overwrite

        // --- stage m tile [d][k0..k0+127] (guarded on last tile) ---
        if (k0 + KT <= KK) {
            for (int f = tid; f < DD * KT / 4; f += NTHREADS) {
                int d  = f >> 5;
                int k4 = (f & 31) << 2;
                float4 v = *reinterpret_cast<const float4*>(
                    cm + (size_t)d * KK + k0 + k4);
                *reinterpret_cast<float4*>(&ms[d * KT + k4]) = v;
            }
        } else {
            for (int f = tid; f < DD * KT; f += NTHREADS) {
                int d = f >> 7;
                int k = f & 127;
                int kg = k0 + k;
                ms[d * KT + k] = (kg < KK) ? cm[(size_t)d * KK + kg] : 0.f;
            }
        }
        if (tid < KT) hs[tid] = g_h[k0 + tid];
        __syncthreads();

        unsigned long long acc[4][8];
#pragma unroll
        for (int p = 0; p < 4; p++)
#pragma unroll
            for (int j = 0; j < 8; j++) acc[p][j] = 0ull;

#pragma unroll 4
        for (int d = 0; d < DD; d++) {
            unsigned long long a[4];
#pragma unroll
            for (int p = 0; p < 4; p++)
                a[p] = *reinterpret_cast<const unsigned long long*>(
                    &xrow[d * XS_STRIDE + 2 * p]);

            float4 b0 = *reinterpret_cast<const float4*>(&mrow[d * KT]);
            float4 b1 = *reinterpret_cast<const float4*>(&mrow[d * KT + 4]);
            float bsc[8] = {b0.x, b0.y, b0.z, b0.w, b1.x, b1.y, b1.z, b1.w};

            unsigned long long bb[8];
#pragma unroll
            for (int j = 0; j < 8; j++)
                asm("mov.b64 %0, {%1, %1};" : "=l"(bb[j]) : "f"(bsc[j]));

#pragma unroll
            for (int j = 0; j < 8; j++)
#pragma unroll
                for (int p = 0; p < 4; p++)
                    asm("fma.rn.f32x2 %0, %1, %2, %0;"
                        : "+l"(acc[p][j]) : "l"(a[p]), "l"(bb[j]));
        }

        // --- dist = h_k - s.m_k ; running argmax (ascending k => first-max) ---
#pragma unroll
        for (int j = 0; j < 8; j++) {
            const int k = k0 + tx * 8 + j;
            const float h = hs[tx * 8 + j];
#pragma unroll
            for (int p = 0; p < 4; p++) {
                float lo = __uint_as_float((unsigned)(acc[p][j] & 0xffffffffull));
                float hi = __uint_as_float((unsigned)(acc[p][j] >> 32));
                float d0 = h - lo;
                float d1 = h - hi;
                if (d0 > best[2 * p])     { best[2 * p] = d0;     bidx[2 * p] = k; }
                if (d1 > best[2 * p + 1]) { best[2 * p + 1] = d1; bidx[2 * p + 1] = k; }
            }
        }
    }

    // --- reduce across the 16 tx-threads (16-lane shfl groups, tie -> min k) ---
#pragma unroll
    for (int i = 0; i < 8; i++) {
        float v = best[i];
        int ix = bidx[i];
#pragma unroll
        for (int off = 8; off; off >>= 1) {
            float ov = __shfl_xor_sync(0xffffffffu, v, off);
            int   oi = __shfl_xor_sync(0xffffffffu, ix, off);
            if (ov > v || (ov == v && oi < ix)) { v = ov; ix = oi; }
        }
        if (tx == 0) {
            int n = n0 + ty * 8 + i;
            g_idx[n] = ix;
            out_idx[n] = (float)ix;
        }
    }
}

// ---------------------------------------------------------------------------
// Kernel 3: gather quantize + per-block partial sums of (x - q)^2
// ---------------------------------------------------------------------------
__global__ void gather_kernel(const float* __restrict__ x,
                              const float* __restrict__ cm,
                              float* __restrict__ out_q) {
    __shared__ float red[256];
    int tid = threadIdx.x;
    float local = 0.f;
    for (int e = blockIdx.x * blockDim.x + tid; e < NS * DD;
         e += gridDim.x * blockDim.x) {
        int n = e >> 7;
        int d = e & 127;
        float q = cm[(size_t)d * KK + g_idx[n]];
        out_q[e] = q;
        float dv = x[e] - q;
        local = fmaf(dv, dv, local);
    }
    red[tid] = local;
    __syncthreads();
    for (int s = 128; s; s >>= 1) {
        if (tid < s) red[tid] += red[tid + s];
        __syncthreads();
    }
    if (tid == 0) g_partial[blockIdx.x] = red[0];
}

// ---------------------------------------------------------------------------
// Kernel 4: deterministic final reduction -> diff scalar
// ---------------------------------------------------------------------------
__global__ void final_kernel(float* __restrict__ out) {
    __shared__ double red[256];
    int tid = threadIdx.x;
    double s = 0.0;
    for (int i = tid; i < 512; i += 256) s += (double)g_partial[i];
    red[tid] = s;
    __syncthreads();
    for (int st = 128; st; st >>= 1) {
        if (tid < st) red[tid] += red[tid + st];
        __syncthreads();
    }
    if (tid == 0)
        out[NS * DD + NS] = (float)(red[0] / (double)((size_t)NS * DD));
}

// ---------------------------------------------------------------------------
extern "C" void kernel_launch(void* const* d_in, const int* in_sizes, int n_in,
                              void* d_out, int out_size) {
    const float* x  = (const float*)d_in[0];   // [16384, 128]
    const float* cm = (const float*)d_in[1];   // [128, 10000]
    float* out = (float*)d_out;                // [quantize | index | diff]

    cudaFuncSetAttribute(argmax_kernel,
                         cudaFuncAttributeMaxDynamicSharedMemorySize,
                         SMEM_BYTES);

    h_kernel<<<(KPAD + 255) / 256, 256>>>(cm);
    argmax_kernel<<<NS / TM, NTHREADS, SMEM_BYTES>>>(x, cm, out + (size_t)NS * DD);
    gather_kernel<<<512, 256>>>(x, cm, out);
    final_kernel<<<1, 256>>>(out);
}

// round 4
// speedup vs baseline: 1.6627x; 1.6627x over previous
#include <cuda_runtime.h>
#include <cuda_bf16.h>
#include <cstdint>

#define NS   16384
#define DD   128
#define KK   10000
#define KT   64
#define NT   157            // 157*64 = 10048
#define KPAD (NT * KT)
#define TM   128

// ---- smem layout (dynamic) ----
#define OFF_A  0            // 3 splits x 32768 = 98304  (x tile, swizzled)
#define OFF_B  98304        // 2 bufs x 49152            (B tile, swizzled)
#define BUFB   49152
#define OFF_H  196608       // 2 x 64 floats
#define SMEM_TOTAL (OFF_H + 512)

__device__ uint4 g_B4[(size_t)NT * 3072];          // pre-split, pre-swizzled B tiles
__device__ __align__(16) float g_h[KPAD];          // 0.5*||m||^2 (pad -> -3e38)
__device__ int   g_idx[NS];
__device__ float g_partial[512];

// ---------------------------------------------------------------------------
__device__ __forceinline__ uint32_t smem_u32(const void* p) {
    uint32_t a;
    asm("{ .reg .u64 t; cvta.to.shared.u64 t, %1; cvt.u32.u64 %0, t; }"
        : "=r"(a) : "l"(p));
    return a;
}
__device__ __forceinline__ void cp16(uint32_t daddr, const void* src) {
    asm volatile("cp.async.cg.shared.global [%0], [%1], 16;"
                 :: "r"(daddr), "l"(src) : "memory");
}
#define CP_COMMIT() asm volatile("cp.async.commit_group;" ::: "memory")

#define LDSM4(R, addr)                                                        \
    asm volatile("ldmatrix.sync.aligned.m8n8.x4.shared.b16 {%0,%1,%2,%3}, [%4];" \
                 : "=r"((R)[0]), "=r"((R)[1]), "=r"((R)[2]), "=r"((R)[3])     \
                 : "r"(addr))

#define MMA(D, A, B0, B1)                                                     \
    asm volatile("mma.sync.aligned.m16n8k16.row.col.f32.bf16.bf16.f32 "       \
                 "{%0,%1,%2,%3}, {%4,%5,%6,%7}, {%8,%9}, {%0,%1,%2,%3};"      \
                 : "+f"((D)[0]), "+f"((D)[1]), "+f"((D)[2]), "+f"((D)[3])     \
                 : "r"((A)[0]), "r"((A)[1]), "r"((A)[2]), "r"((A)[3]),        \
                   "r"(B0), "r"(B1))

__device__ __forceinline__ unsigned pk(float a, float b) {
    __nv_bfloat162 t = __floats2bfloat162_rn(a, b);
    return *reinterpret_cast<unsigned*>(&t);
}

// ---------------------------------------------------------------------------
// prep: split cluster means into (hi, mid, lo) bf16 and write the SWIZZLED
// [n][k] tile images (rows = clusters, 256B rows, chunk c' = c ^ (n&7)).
// ---------------------------------------------------------------------------
__global__ void prepB_kernel(const float* __restrict__ cm) {
    int idx = blockIdx.x * blockDim.x + threadIdx.x;
    if (idx >= NT * 1024) return;
    int t = idx >> 10;
    int n = (idx >> 4) & 63;
    int c = idx & 15;
    int kg = t * KT + n;

    float v[8];
#pragma unroll
    for (int j = 0; j < 8; j++) {
        int d = c * 8 + j;
        v[j] = (kg < KK) ? cm[(size_t)d * KK + kg] : 0.f;
    }
    uint4 H, M, L;
    uint32_t* hp = &H.x; uint32_t* mp = &M.x; uint32_t* lp = &L.x;
#pragma unroll
    for (int j = 0; j < 4; j++) {
        float v0 = v[2 * j], v1 = v[2 * j + 1];
        float h0 = __bfloat162float(__float2bfloat16(v0));
        float h1 = __bfloat162float(__float2bfloat16(v1));
        float r0 = v0 - h0, r1 = v1 - h1;
        float m0 = __bfloat162float(__float2bfloat16(r0));
        float m1 = __bfloat162float(__float2bfloat16(r1));
        hp[j] = pk(v0, v1);
        mp[j] = pk(r0, r1);
        lp[j] = pk(r0 - m0, r1 - m1);
    }
    int ci = n * 16 + (c ^ (n & 7));                 // uint4 index within split
    size_t base = (size_t)t * 3072 + ci;
    g_B4[base]        = H;
    g_B4[base + 1024] = M;                           // +16384B
    g_B4[base + 2048] = L;                           // +32768B
}

__global__ void h_kernel(const float* __restrict__ cm) {
    int k = blockIdx.x * blockDim.x + threadIdx.x;
    if (k >= KPAD) return;
    if (k < KK) {
        float s = 0.f;
#pragma unroll 8
        for (int d = 0; d < DD; d++) {
            float v = cm[(size_t)d * KK + k];
            s = fmaf(v, v, s);
        }
        g_h[k] = 0.5f * s;
    } else {
        g_h[k] = -3.0e38f;
    }
}

// ---------------------------------------------------------------------------
// main: 128 samples/CTA; 6-way bf16-split GEMM via mma.sync + running argmax.
// ---------------------------------------------------------------------------
__global__ void __launch_bounds__(256, 1)
vq_main(const float* __restrict__ x, float* __restrict__ out_idx_f) {
    extern __shared__ __align__(1024) char smem[];
    const uint32_t sb = smem_u32(smem);
    const int tid = threadIdx.x;
    const int wid = tid >> 5;
    const int lane = tid & 31;
    const int l8 = lane & 7;
    const int g = lane >> 3;
    const int mwarp = wid >> 2;
    const int nwarp = wid & 3;
    const int n0 = blockIdx.x * TM;

    // kick off first B stage before doing anything else
    {
        const uint4* src = g_B4;
        uint32_t dst = sb + OFF_B;
#pragma unroll
        for (int i = 0; i < 12; i++)
            cp16(dst + (uint32_t)(tid + i * 256) * 16, src + tid + i * 256);
        if (tid < 16)
            cp16(sb + OFF_H + tid * 16, (const char*)g_h + tid * 16);
        CP_COMMIT();
    }

    // ---- A prologue: split x rows into 3 bf16 tiles, swizzled in smem ----
    {
        const int row = tid >> 1;
        const int c0 = (tid & 1) * 8;
        const float4* xr = reinterpret_cast<const float4*>(x + (size_t)(n0 + row) * DD);
        uint4* As = reinterpret_cast<uint4*>(smem + OFF_A);
#pragma unroll
        for (int c = 0; c < 8; c++) {
            float4 p = xr[(c0 + c) * 2];
            float4 q = xr[(c0 + c) * 2 + 1];
            float v[8] = {p.x, p.y, p.z, p.w, q.x, q.y, q.z, q.w};
            uint4 H, M, L;
            uint32_t* hp = &H.x; uint32_t* mp = &M.x; uint32_t* lp = &L.x;
#pragma unroll
            for (int j = 0; j < 4; j++) {
                float v0 = v[2 * j], v1 = v[2 * j + 1];
                float h0 = __bfloat162float(__float2bfloat16(v0));
                float h1 = __bfloat162float(__float2bfloat16(v1));
                float r0 = v0 - h0, r1 = v1 - h1;
                float m0 = __bfloat162float(__float2bfloat16(r0));
                float m1 = __bfloat162float(__float2bfloat16(r1));
                hp[j] = pk(v0, v1);
                mp[j] = pk(r0, r1);
                lp[j] = pk(r0 - m0, r1 - m1);
            }
            int ci = row * 16 + ((c0 + c) ^ (row & 7));
            As[ci] = H;
            As[ci + 2048] = M;    // +32768 B
            As[ci + 4096] = L;    // +65536 B
        }
    }

    // per-lane address bases (XOR-fold swizzle)
    // FIX (round 3): include the per-warp tile offsets that were missing.
    //   A: mwarp selects 64-row block  -> + mwarp * 64 * 256B = mwarp * 16384
    //   B: nwarp selects 16-col block  -> + nwarp * 16 * 256B = nwarp * 4096
    const uint32_t AQ  = sb + OFF_A + (uint32_t)mwarp * 16384u
                       + (uint32_t)l8 * 272 + ((uint32_t)(g & 1) << 11);
    const uint32_t gxa = (uint32_t)(g >> 1) << 4;
    const uint32_t gxb = (uint32_t)(g & 1) << 4;
    const uint32_t BQg = (uint32_t)nwarp * 4096u
                       + ((uint32_t)(g >> 1) << 11) + (uint32_t)l8 * 272;

    float best8[8];
    int   idx8[8];
#pragma unroll
    for (int i = 0; i < 8; i++) { best8[i] = -3.4e38f; idx8[i] = 0; }

    for (int t = 0; t < NT; t++) {
        const int b = t & 1;

        if (t + 1 < NT) {           // prefetch next tile into the other buffer
            const uint4* src = g_B4 + (size_t)(t + 1) * 3072;
            uint32_t dst = sb + OFF_B + (uint32_t)((t + 1) & 1) * BUFB;
#pragma unroll
            for (int i = 0; i < 12; i++)
                cp16(dst + (uint32_t)(tid + i * 256) * 16, src + tid + i * 256);
            if (tid < 16)
                cp16(sb + OFF_H + (uint32_t)((t + 1) & 1) * 256 + tid * 16,
                     (const char*)g_h + (size_t)(t + 1) * 256 + tid * 16);
            CP_COMMIT();
            asm volatile("cp.async.wait_group 1;" ::: "memory");
        } else {
            asm volatile("cp.async.wait_group 0;" ::: "memory");
        }
        __syncthreads();

        // ---- compute tile t on buffer b ----
        const uint32_t Bt = sb + OFF_B + (uint32_t)b * BUFB + BQg;
        float acc[4][2][4];
#pragma unroll
        for (int ma = 0; ma < 4; ma++)
#pragma unroll
            for (int na = 0; na < 2; na++)
#pragma unroll
                for (int r = 0; r < 4; r++) acc[ma][na][r] = 0.f;

#pragma unroll
        for (int ks = 0; ks < 8; ks++) {
            const uint32_t kxa = ((uint32_t)ks << 5) | gxa;
            const uint32_t kxb = ((uint32_t)ks << 5) | gxb;
            uint32_t a[3][4][4];
            uint32_t bf[3][4];
#pragma unroll
            for (int s = 0; s < 3; s++)
#pragma unroll
                for (int ma = 0; ma < 4; ma++)
                    LDSM4(a[s][ma],
                          (AQ + (uint32_t)s * 32768 + (uint32_t)ma * 4096) ^ kxa);
#pragma unroll
            for (int s = 0; s < 3; s++)
                LDSM4(bf[s], (Bt + (uint32_t)s * 16384) ^ kxb);

            const int pa[6] = {0, 0, 1, 1, 0, 2};
            const int pb[6] = {0, 1, 0, 1, 2, 0};
#pragma unroll
            for (int p = 0; p < 6; p++)
#pragma unroll
                for (int ma = 0; ma < 4; ma++)
#pragma unroll
                    for (int na = 0; na < 2; na++)
                        MMA(acc[ma][na], a[pa[p]][ma],
                            bf[pb[p]][2 * na], bf[pb[p]][2 * na + 1]);
        }

        // ---- running argmax on dist_rank = h_k - s.m_k ----
        const float* hb = reinterpret_cast<const float*>(smem + OFF_H + b * 256);
        const int colb = t * KT + nwarp * 16 + (lane & 3) * 2;
#pragma unroll
        for (int na = 0; na < 2; na++) {
            const int hi0 = nwarp * 16 + na * 8 + (lane & 3) * 2;
            const float h0 = hb[hi0];
            const float h1 = hb[hi0 + 1];
            const int c0 = colb + na * 8;
#pragma unroll
            for (int ma = 0; ma < 4; ma++) {
                float d0 = h0 - acc[ma][na][0];
                float d1 = h1 - acc[ma][na][1];
                float d2 = h0 - acc[ma][na][2];
                float d3 = h1 - acc[ma][na][3];
                const int s0 = ma * 2, s1 = ma * 2 + 1;
                if (d0 > best8[s0]) { best8[s0] = d0; idx8[s0] = c0; }
                if (d1 > best8[s0]) { best8[s0] = d1; idx8[s0] = c0 + 1; }
                if (d2 > best8[s1]) { best8[s1] = d2; idx8[s1] = c0; }
                if (d3 > best8[s1]) { best8[s1] = d3; idx8[s1] = c0 + 1; }
            }
        }
        __syncthreads();   // done reading buf b before it is overwritten
    }

    // ---- merge: 4 column-lanes -> 4 n-warps -> final ----
    float* sbv = reinterpret_cast<float*>(smem);
    int*   siv = reinterpret_cast<int*>(smem + 2048);
#pragma unroll
    for (int s = 0; s < 8; s++) {
        float v = best8[s];
        int ix = idx8[s];
#pragma unroll
        for (int off = 1; off < 4; off <<= 1) {
            float ov = __shfl_xor_sync(0xffffffffu, v, off);
            int   oi = __shfl_xor_sync(0xffffffffu, ix, off);
            if (ov > v || (ov == v && oi < ix)) { v = ov; ix = oi; }
        }
        if ((lane & 3) == 0) {
            int row = mwarp * 64 + (s >> 1) * 16 + (s & 1) * 8 + (lane >> 2);
            sbv[row * 4 + nwarp] = v;
            siv[row * 4 + nwarp] = ix;
        }
    }
    __syncthreads();
    if (tid < 128) {
        float bv = sbv[tid * 4];
        int bi = siv[tid * 4];
#pragma unroll
        for (int w = 1; w < 4; w++) {
            float v = sbv[tid * 4 + w];
            int ix = siv[tid * 4 + w];
            if (v > bv || (v == bv && ix < bi)) { bv = v; bi = ix; }
        }
        g_idx[n0 + tid] = bi;
        out_idx_f[n0 + tid] = (float)bi;
    }
}

// ---------------------------------------------------------------------------
__global__ void gather_kernel(const float* __restrict__ x,
                              const float* __restrict__ cm,
                              float* __restrict__ out_q) {
    __shared__ float red[256];
    int tid = threadIdx.x;
    float local = 0.f;
    for (int e = blockIdx.x * blockDim.x + tid; e < NS * DD;
         e += gridDim.x * blockDim.x) {
        int n = e >> 7;
        int d = e & 127;
        float q = cm[(size_t)d * KK + g_idx[n]];
        out_q[e] = q;
        float dv = x[e] - q;
        local = fmaf(dv, dv, local);
    }
    red[tid] = local;
    __syncthreads();
    for (int s = 128; s; s >>= 1) {
        if (tid < s) red[tid] += red[tid + s];
        __syncthreads();
    }
    if (tid == 0) g_partial[blockIdx.x] = red[0];
}

__global__ void final_kernel(float* __restrict__ out) {
    __shared__ double red[256];
    int tid = threadIdx.x;
    double s = 0.0;
    for (int i = tid; i < 512; i += 256) s += (double)g_partial[i];
    red[tid] = s;
    __syncthreads();
    for (int st = 128; st; st >>= 1) {
        if (tid < st) red[tid] += red[tid + st];
        __syncthreads();
    }
    if (tid == 0)
        out[NS * DD + NS] = (float)(red[0] / (double)((size_t)NS * DD));
}

// ---------------------------------------------------------------------------
extern "C" void kernel_launch(void* const* d_in, const int* in_sizes, int n_in,
                              void* d_out, int out_size) {
    const float* x  = (const float*)d_in[0];   // [16384, 128]
    const float* cm = (const float*)d_in[1];   // [128, 10000]
    float* out = (float*)d_out;                // [quantize | index | diff]

    cudaFuncSetAttribute(vq_main,
                         cudaFuncAttributeMaxDynamicSharedMemorySize, SMEM_TOTAL);

    prepB_kernel<<<(NT * 1024 + 255) / 256, 256>>>(cm);
    h_kernel<<<(KPAD + 255) / 256, 256>>>(cm);
    vq_main<<<NS / TM, 256, SMEM_TOTAL>>>(x, out + (size_t)NS * DD);
    gather_kernel<<<512, 256>>>(x, cm, out);
    final_kernel<<<1, 256>>>(out);
}

// round 5
// speedup vs baseline: 2.4500x; 1.4735x over previous
#include <cuda_runtime.h>
#include <cuda_fp16.h>
#include <cstdint>

#define NS   16384
#define DD   128
#define KK   10000
#define KT   128
#define NT2  79             // 79*128 = 10112
#define KPAD (NT2 * KT)
#define TM   128

// ---- smem layout (vq_main, dynamic) ----
#define OFF_A  0            // 2 splits x 32768 = 65536 (x tile, swizzled fp16)
#define OFF_B  65536        // 2 bufs x 65536           (B tile: [split0|split1])
#define BUFB   65536
#define OFF_H  196608       // 2 x 128 floats
#define SMEM_TOTAL (OFF_H + 1024)

__device__ uint4 g_B4[(size_t)NT2 * 4096];   // pre-split(2xfp16), pre-swizzled B tiles
__device__ __align__(16) float g_cmT[(size_t)KPAD * DD];  // transposed means [k][d]
__device__ __align__(16) float g_h[KPAD];    // 0.5*||m||^2 (pad -> -3e38)
__device__ int   g_idx[NS];
__device__ float g_partial[512];

// ---------------------------------------------------------------------------
__device__ __forceinline__ uint32_t smem_u32(const void* p) {
    uint32_t a;
    asm("{ .reg .u64 t; cvta.to.shared.u64 t, %1; cvt.u32.u64 %0, t; }"
        : "=r"(a) : "l"(p));
    return a;
}
__device__ __forceinline__ void cp16(uint32_t daddr, const void* src) {
    asm volatile("cp.async.cg.shared.global [%0], [%1], 16;"
                 :: "r"(daddr), "l"(src) : "memory");
}
#define CP_COMMIT() asm volatile("cp.async.commit_group;" ::: "memory")

#define LDSM4(R, addr)                                                        \
    asm volatile("ldmatrix.sync.aligned.m8n8.x4.shared.b16 {%0,%1,%2,%3}, [%4];" \
                 : "=r"((R)[0]), "=r"((R)[1]), "=r"((R)[2]), "=r"((R)[3])     \
                 : "r"(addr))

#define MMA(D, A, B0, B1)                                                     \
    asm volatile("mma.sync.aligned.m16n8k16.row.col.f32.f16.f16.f32 "         \
                 "{%0,%1,%2,%3}, {%4,%5,%6,%7}, {%8,%9}, {%0,%1,%2,%3};"      \
                 : "+f"((D)[0]), "+f"((D)[1]), "+f"((D)[2]), "+f"((D)[3])     \
                 : "r"((A)[0]), "r"((A)[1]), "r"((A)[2]), "r"((A)[3]),        \
                   "r"(B0), "r"(B1))

__device__ __forceinline__ unsigned pk2h(float a, float b) {
    __half2 t = __floats2half2_rn(a, b);
    return *reinterpret_cast<unsigned*>(&t);
}

// ---------------------------------------------------------------------------
// prep: per 32-cluster sub-tile, smem-transpose cm, emit (hi, mid) fp16 split
// tiles in the swizzled ldmatrix image, plus a transposed fp32 copy g_cmT.
// grid = NT2*4 blocks x 256 threads.
// ---------------------------------------------------------------------------
__global__ void prepB_kernel(const float* __restrict__ cm) {
    __shared__ float st[32][132];
    const int t = blockIdx.x >> 2;
    const int sub = blockIdx.x & 3;
    const int kbase = t * KT + sub * 32;
    const int tid = threadIdx.x;

    if (kbase + 32 <= KK) {
        // vectorized: 128 d x 8 float4
#pragma unroll
        for (int i = 0; i < 4; i++) {
            int it = tid + i * 256;
            int d = it >> 3;
            int k4 = (it & 7) * 4;
            float4 v = *reinterpret_cast<const float4*>(cm + (size_t)d * KK + kbase + k4);
            st[k4 + 0][d] = v.x;
            st[k4 + 1][d] = v.y;
            st[k4 + 2][d] = v.z;
            st[k4 + 3][d] = v.w;
        }
    } else {
#pragma unroll
        for (int i = 0; i < 16; i++) {
            int it = tid + i * 256;
            int d = it >> 5;
            int k = it & 31;
            st[k][d] = (kbase + k < KK) ? cm[(size_t)d * KK + kbase + k] : 0.f;
        }
    }
    __syncthreads();

    // fp16 2-way split + pack, swizzled image
#pragma unroll
    for (int i = 0; i < 2; i++) {
        int it = tid + i * 256;
        int n = it >> 4;
        int c = it & 15;
        uint4 H, M;
        uint32_t* hp = &H.x; uint32_t* mp = &M.x;
#pragma unroll
        for (int j = 0; j < 4; j++) {
            float v0 = st[n][c * 8 + 2 * j];
            float v1 = st[n][c * 8 + 2 * j + 1];
            __half h0 = __float2half_rn(v0);
            __half h1 = __float2half_rn(v1);
            float r0 = v0 - __half2float(h0);
            float r1 = v1 - __half2float(h1);
            hp[j] = pk2h(v0, v1);
            mp[j] = pk2h(r0, r1);
        }
        int r = sub * 32 + n;                        // row within tile
        int ci = r * 16 + (c ^ (r & 7));
        size_t base = (size_t)t * 4096 + ci;
        g_B4[base]        = H;
        g_B4[base + 2048] = M;
    }

    // transposed fp32 copy (coalesced rows for gather)
#pragma unroll
    for (int i = 0; i < 4; i++) {
        int it = tid + i * 256;
        int n = it >> 5;
        int d4 = (it & 31) * 4;
        float4 w = make_float4(st[n][d4], st[n][d4 + 1], st[n][d4 + 2], st[n][d4 + 3]);
        *reinterpret_cast<float4*>(g_cmT + (size_t)(kbase + n) * DD + d4) = w;
    }
}

__global__ void h_kernel(const float* __restrict__ cm) {
    int k = blockIdx.x * blockDim.x + threadIdx.x;
    if (k >= KPAD) return;
    if (k < KK) {
        float s = 0.f;
#pragma unroll 8
        for (int d = 0; d < DD; d++) {
            float v = cm[(size_t)d * KK + k];
            s = fmaf(v, v, s);
        }
        g_h[k] = 0.5f * s;
    } else {
        g_h[k] = -3.0e38f;
    }
}

// ---------------------------------------------------------------------------
// main: 128 samples/CTA; 4-product fp16-split GEMM via mma.sync + argmax.
// ---------------------------------------------------------------------------
__global__ void __launch_bounds__(256, 1)
vq_main(const float* __restrict__ x, float* __restrict__ out_idx_f) {
    extern __shared__ __align__(1024) char smem[];
    const uint32_t sb = smem_u32(smem);
    const int tid = threadIdx.x;
    const int wid = tid >> 5;
    const int lane = tid & 31;
    const int l8 = lane & 7;
    const int g = lane >> 3;
    const int mwarp = wid >> 2;
    const int nwarp = wid & 3;
    const int n0 = blockIdx.x * TM;

    // stage tile 0 immediately
    {
        const uint4* src = g_B4;
        uint32_t dst = sb + OFF_B;
#pragma unroll
        for (int i = 0; i < 16; i++)
            cp16(dst + (uint32_t)(tid + i * 256) * 16, src + tid + i * 256);
        if (tid < 32)
            cp16(sb + OFF_H + tid * 16, (const char*)g_h + tid * 16);
        CP_COMMIT();
    }

    // ---- A prologue: fp16 2-way split of x rows, swizzled in smem ----
    {
        const int row = tid >> 1;
        const int c0 = (tid & 1) * 8;
        const float4* xr = reinterpret_cast<const float4*>(x + (size_t)(n0 + row) * DD);
        uint4* As = reinterpret_cast<uint4*>(smem + OFF_A);
#pragma unroll
        for (int c = 0; c < 8; c++) {
            float4 p = xr[(c0 + c) * 2];
            float4 q = xr[(c0 + c) * 2 + 1];
            float v[8] = {p.x, p.y, p.z, p.w, q.x, q.y, q.z, q.w};
            uint4 H, M;
            uint32_t* hp = &H.x; uint32_t* mp = &M.x;
#pragma unroll
            for (int j = 0; j < 4; j++) {
                float v0 = v[2 * j], v1 = v[2 * j + 1];
                __half h0 = __float2half_rn(v0);
                __half h1 = __float2half_rn(v1);
                float r0 = v0 - __half2float(h0);
                float r1 = v1 - __half2float(h1);
                hp[j] = pk2h(v0, v1);
                mp[j] = pk2h(r0, r1);
            }
            int ci = row * 16 + ((c0 + c) ^ (row & 7));
            As[ci] = H;
            As[ci + 2048] = M;     // +32768 B
        }
    }

    // per-lane address bases (XOR-fold swizzle)
    const uint32_t AQ  = sb + OFF_A + (uint32_t)mwarp * 16384u
                       + (uint32_t)l8 * 272 + ((uint32_t)(g & 1) << 11);
    const uint32_t gxa = (uint32_t)(g >> 1) << 4;
    const uint32_t gxb = (uint32_t)(g & 1) << 4;
    const uint32_t BQg = (uint32_t)nwarp * 8192u
                       + ((uint32_t)(g >> 1) << 11) + (uint32_t)l8 * 272;

    float best8[8];
    int   idx8[8];
#pragma unroll
    for (int i = 0; i < 8; i++) { best8[i] = -3.4e38f; idx8[i] = 0; }

    for (int t = 0; t < NT2; t++) {
        const int b = t & 1;

        if (t + 1 < NT2) {          // prefetch next tile into the other buffer
            const uint4* src = g_B4 + (size_t)(t + 1) * 4096;
            uint32_t dst = sb + OFF_B + (uint32_t)((t + 1) & 1) * BUFB;
#pragma unroll
            for (int i = 0; i < 16; i++)
                cp16(dst + (uint32_t)(tid + i * 256) * 16, src + tid + i * 256);
            if (tid < 32)
                cp16(sb + OFF_H + (uint32_t)((t + 1) & 1) * 512 + tid * 16,
                     (const char*)g_h + (size_t)(t + 1) * 512 + tid * 16);
            CP_COMMIT();
            asm volatile("cp.async.wait_group 1;" ::: "memory");
        } else {
            asm volatile("cp.async.wait_group 0;" ::: "memory");
        }
        __syncthreads();

        // ---- compute tile t on buffer b ----
        const uint32_t Bt = sb + OFF_B + (uint32_t)b * BUFB + BQg;
        float acc[4][4][4];
#pragma unroll
        for (int ma = 0; ma < 4; ma++)
#pragma unroll
            for (int nn = 0; nn < 4; nn++)
#pragma unroll
                for (int r = 0; r < 4; r++) acc[ma][nn][r] = 0.f;

#pragma unroll
        for (int ks = 0; ks < 8; ks++) {
            const uint32_t kxa = ((uint32_t)ks << 5) | gxa;
            const uint32_t kxb = ((uint32_t)ks << 5) | gxb;
            uint32_t a[2][4][4];
            uint32_t bf[2][2][4];
#pragma unroll
            for (int s = 0; s < 2; s++)
#pragma unroll
                for (int ma = 0; ma < 4; ma++)
                    LDSM4(a[s][ma],
                          (AQ + (uint32_t)s * 32768 + (uint32_t)ma * 4096) ^ kxa);
#pragma unroll
            for (int s = 0; s < 2; s++)
#pragma unroll
                for (int nb = 0; nb < 2; nb++)
                    LDSM4(bf[s][nb],
                          (Bt + (uint32_t)s * 32768 + (uint32_t)nb * 4096) ^ kxb);

#pragma unroll
            for (int pa = 0; pa < 2; pa++)
#pragma unroll
                for (int pb = 0; pb < 2; pb++)
#pragma unroll
                    for (int ma = 0; ma < 4; ma++)
#pragma unroll
                        for (int nn = 0; nn < 4; nn++)
                            MMA(acc[ma][nn], a[pa][ma],
                                bf[pb][nn >> 1][2 * (nn & 1)],
                                bf[pb][nn >> 1][2 * (nn & 1) + 1]);
        }

        // ---- running argmax on dist_rank = h_k - s.m_k ----
        const float* hb = reinterpret_cast<const float*>(smem + OFF_H + b * 512);
#pragma unroll
        for (int nn = 0; nn < 4; nn++) {
            const int hi0 = nwarp * 32 + nn * 8 + (lane & 3) * 2;
            const float h0 = hb[hi0];
            const float h1 = hb[hi0 + 1];
            const int c0 = t * KT + hi0;
#pragma unroll
            for (int ma = 0; ma < 4; ma++) {
                float d0 = h0 - acc[ma][nn][0];
                float d1 = h1 - acc[ma][nn][1];
                float d2 = h0 - acc[ma][nn][2];
                float d3 = h1 - acc[ma][nn][3];
                const int s0 = ma * 2, s1 = ma * 2 + 1;
                if (d0 > best8[s0]) { best8[s0] = d0; idx8[s0] = c0; }
                if (d1 > best8[s0]) { best8[s0] = d1; idx8[s0] = c0 + 1; }
                if (d2 > best8[s1]) { best8[s1] = d2; idx8[s1] = c0; }
                if (d3 > best8[s1]) { best8[s1] = d3; idx8[s1] = c0 + 1; }
            }
        }
        __syncthreads();   // done reading buf b before it is overwritten
    }

    // ---- merge: 4 column-lanes -> 4 n-warps -> final ----
    float* sbv = reinterpret_cast<float*>(smem);
    int*   siv = reinterpret_cast<int*>(smem + 2048);
#pragma unroll
    for (int s = 0; s < 8; s++) {
        float v = best8[s];
        int ix = idx8[s];
#pragma unroll
        for (int off = 1; off < 4; off <<= 1) {
            float ov = __shfl_xor_sync(0xffffffffu, v, off);
            int   oi = __shfl_xor_sync(0xffffffffu, ix, off);
            if (ov > v || (ov == v && oi < ix)) { v = ov; ix = oi; }
        }
        if ((lane & 3) == 0) {
            int row = mwarp * 64 + (s >> 1) * 16 + (s & 1) * 8 + (lane >> 2);
            sbv[row * 4 + nwarp] = v;
            siv[row * 4 + nwarp] = ix;
        }
    }
    __syncthreads();
    if (tid < 128) {
        float bv = sbv[tid * 4];
        int bi = siv[tid * 4];
#pragma unroll
        for (int w = 1; w < 4; w++) {
            float v = sbv[tid * 4 + w];
            int ix = siv[tid * 4 + w];
            if (v > bv || (v == bv && ix < bi)) { bv = v; bi = ix; }
        }
        g_idx[n0 + tid] = bi;
        out_idx_f[n0 + tid] = (float)bi;
    }
}

// ---------------------------------------------------------------------------
// gather quantize (coalesced via g_cmT) + partial MSE sums
// ---------------------------------------------------------------------------
__global__ void gather_kernel(const float* __restrict__ x,
                              float* __restrict__ out_q) {
    __shared__ float red[256];
    int tid = threadIdx.x;
    float local = 0.f;
    for (int e4 = blockIdx.x * blockDim.x + tid; e4 < NS * DD / 4;
         e4 += gridDim.x * blockDim.x) {
        int n = e4 >> 5;
        int d4 = (e4 & 31) * 4;
        float4 q = *reinterpret_cast<const float4*>(
            g_cmT + (size_t)g_idx[n] * DD + d4);
        float4 xv = reinterpret_cast<const float4*>(x)[e4];
        reinterpret_cast<float4*>(out_q)[e4] = q;
        float a = xv.x - q.x, bb = xv.y - q.y, c = xv.z - q.z, dd = xv.w - q.w;
        local = fmaf(a, a, local);
        local = fmaf(bb, bb, local);
        local = fmaf(c, c, local);
        local = fmaf(dd, dd, local);
    }
    red[tid] = local;
    __syncthreads();
    for (int s = 128; s; s >>= 1) {
        if (tid < s) red[tid] += red[tid + s];
        __syncthreads();
    }
    if (tid == 0) g_partial[blockIdx.x] = red[0];
}

__global__ void final_kernel(float* __restrict__ out) {
    __shared__ double red[256];
    int tid = threadIdx.x;
    double s = 0.0;
    for (int i = tid; i < 512; i += 256) s += (double)g_partial[i];
    red[tid] = s;
    __syncthreads();
    for (int st = 128; st; st >>= 1) {
        if (tid < st) red[tid] += red[tid + st];
        __syncthreads();
    }
    if (tid == 0)
        out[NS * DD + NS] = (float)(red[0] / (double)((size_t)NS * DD));
}

// ---------------------------------------------------------------------------
extern "C" void kernel_launch(void* const* d_in, const int* in_sizes, int n_in,
                              void* d_out, int out_size) {
    const float* x  = (const float*)d_in[0];   // [16384, 128]
    const float* cm = (const float*)d_in[1];   // [128, 10000]
    float* out = (float*)d_out;                // [quantize | index | diff]

    cudaFuncSetAttribute(vq_main,
                         cudaFuncAttributeMaxDynamicSharedMemorySize, SMEM_TOTAL);

    prepB_kernel<<<NT2 * 4, 256>>>(cm);
    h_kernel<<<(KPAD + 255) / 256, 256>>>(cm);
    vq_main<<<NS / TM, 256, SMEM_TOTAL>>>(x, out + (size_t)NS * DD);
    gather_kernel<<<512, 256>>>(x, out);
    final_kernel<<<1, 256>>>(out);
}

// round 6
// speedup vs baseline: 3.3726x; 1.3766x over previous
#include <cuda_runtime.h>
#include <cuda_fp16.h>
#include <cstdint>

#define NS   16384
#define DD   128
#define KK   10000
#define KT   128
#define NT2  79             // 79*128 = 10112
#define KPAD (NT2 * KT)
#define TM   128
#define NST  128            // sample tiles
#define NUNITS (NST * NT2)  // 10112 work units
#define GRID 148

// ---- smem layout (vq_main, dynamic) ----
#define OFF_A  0            // 2 splits x 32768 = 65536 (x tile, swizzled fp16)
#define OFF_B  65536        // 2 bufs x 65536           (B tile: [split0|split1])
#define BUFB   65536
#define OFF_H  196608       // 2 x 128 floats
#define SMEM_TOTAL (OFF_H + 1024)

__device__ uint4 g_B4[(size_t)NT2 * 4096];   // pre-split(2xfp16), pre-swizzled B tiles
__device__ __align__(16) float g_cmT[(size_t)KPAD * DD];  // transposed means [k][d]
__device__ __align__(16) float g_h[KPAD];    // 0.5*||m||^2 (pad -> -3e38)
__device__ unsigned long long g_best[NS];    // (dist_key<<32)|(~idx) via atomicMax
__device__ int   g_idx[NS];
__device__ float g_partial[512];

// ---------------------------------------------------------------------------
__device__ __forceinline__ uint32_t smem_u32(const void* p) {
    uint32_t a;
    asm("{ .reg .u64 t; cvta.to.shared.u64 t, %1; cvt.u32.u64 %0, t; }"
        : "=r"(a) : "l"(p));
    return a;
}
__device__ __forceinline__ void cp16(uint32_t daddr, const void* src) {
    asm volatile("cp.async.cg.shared.global [%0], [%1], 16;"
                 :: "r"(daddr), "l"(src) : "memory");
}
#define CP_COMMIT() asm volatile("cp.async.commit_group;" ::: "memory")

#define LDSM4(R, addr)                                                        \
    asm volatile("ldmatrix.sync.aligned.m8n8.x4.shared.b16 {%0,%1,%2,%3}, [%4];" \
                 : "=r"((R)[0]), "=r"((R)[1]), "=r"((R)[2]), "=r"((R)[3])     \
                 : "r"(addr))

#define MMA(D, A, B0, B1)                                                     \
    asm volatile("mma.sync.aligned.m16n8k16.row.col.f32.f16.f16.f32 "         \
                 "{%0,%1,%2,%3}, {%4,%5,%6,%7}, {%8,%9}, {%0,%1,%2,%3};"      \
                 : "+f"((D)[0]), "+f"((D)[1]), "+f"((D)[2]), "+f"((D)[3])     \
                 : "r"((A)[0]), "r"((A)[1]), "r"((A)[2]), "r"((A)[3]),        \
                   "r"(B0), "r"(B1))

__device__ __forceinline__ unsigned pk2h(float a, float b) {
    __half2 t = __floats2half2_rn(a, b);
    return *reinterpret_cast<unsigned*>(&t);
}
__device__ __forceinline__ unsigned enc_f(float f) {
    unsigned s = __float_as_uint(f);
    return (s & 0x80000000u) ? ~s : (s | 0x80000000u);
}

// ---------------------------------------------------------------------------
// prep: per 32-cluster sub-tile: smem-transpose cm; emit (hi, mid) fp16 split
// tiles in the swizzled ldmatrix image; transposed fp32 copy g_cmT; h values;
// and zero g_best for this launch (graph-replay safe).
// grid = NT2*4 = 316 blocks x 256 threads.
// ---------------------------------------------------------------------------
__global__ void prepB_kernel(const float* __restrict__ cm) {
    __shared__ float st[32][132];
    const int t = blockIdx.x >> 2;
    const int sub = blockIdx.x & 3;
    const int kbase = t * KT + sub * 32;
    const int tid = threadIdx.x;

    int gtid = blockIdx.x * 256 + tid;
    if (gtid < NS) g_best[gtid] = 0ull;

    if (kbase + 32 <= KK) {
#pragma unroll
        for (int i = 0; i < 4; i++) {
            int it = tid + i * 256;
            int d = it >> 3;
            int k4 = (it & 7) * 4;
            float4 v = *reinterpret_cast<const float4*>(cm + (size_t)d * KK + kbase + k4);
            st[k4 + 0][d] = v.x;
            st[k4 + 1][d] = v.y;
            st[k4 + 2][d] = v.z;
            st[k4 + 3][d] = v.w;
        }
    } else {
#pragma unroll
        for (int i = 0; i < 16; i++) {
            int it = tid + i * 256;
            int d = it >> 5;
            int k = it & 31;
            st[k][d] = (kbase + k < KK) ? cm[(size_t)d * KK + kbase + k] : 0.f;
        }
    }
    __syncthreads();

    // h = 0.5*||m||^2 (8 lanes per cluster row, shfl-reduce)
    {
        int n = tid >> 3, part = tid & 7;
        float s = 0.f;
#pragma unroll
        for (int j = 0; j < 16; j++) {
            float v = st[n][part * 16 + j];
            s = fmaf(v, v, s);
        }
#pragma unroll
        for (int off = 4; off; off >>= 1)
            s += __shfl_down_sync(0xffffffffu, s, off);
        if (part == 0)
            g_h[kbase + n] = (kbase + n < KK) ? 0.5f * s : -3.0e38f;
    }

    // fp16 2-way split + pack, swizzled image
#pragma unroll
    for (int i = 0; i < 2; i++) {
        int it = tid + i * 256;
        int n = it >> 4;
        int c = it & 15;
        uint4 H, M;
        uint32_t* hp = &H.x; uint32_t* mp = &M.x;
#pragma unroll
        for (int j = 0; j < 4; j++) {
            float v0 = st[n][c * 8 + 2 * j];
            float v1 = st[n][c * 8 + 2 * j + 1];
            __half h0 = __float2half_rn(v0);
            __half h1 = __float2half_rn(v1);
            float r0 = v0 - __half2float(h0);
            float r1 = v1 - __half2float(h1);
            hp[j] = pk2h(v0, v1);
            mp[j] = pk2h(r0, r1);
        }
        int r = sub * 32 + n;
        int ci = r * 16 + (c ^ (r & 7));
        size_t base = (size_t)t * 4096 + ci;
        g_B4[base]        = H;
        g_B4[base + 2048] = M;
    }

    // transposed fp32 copy (coalesced rows for gather)
#pragma unroll
    for (int i = 0; i < 4; i++) {
        int it = tid + i * 256;
        int n = it >> 5;
        int d4 = (it & 31) * 4;
        float4 w = make_float4(st[n][d4], st[n][d4 + 1], st[n][d4 + 2], st[n][d4 + 3]);
        *reinterpret_cast<float4*>(g_cmT + (size_t)(kbase + n) * DD + d4) = w;
    }
}

// ---------------------------------------------------------------------------
__device__ __forceinline__ void stageB_fn(uint32_t sb, int tid, int kc, int buf) {
    const uint4* src = g_B4 + (size_t)kc * 4096;
    uint32_t dst = sb + OFF_B + (uint32_t)buf * BUFB;
#pragma unroll
    for (int i = 0; i < 16; i++)
        cp16(dst + (uint32_t)(tid + i * 256) * 16, src + tid + i * 256);
    if (tid < 32)
        cp16(sb + OFF_H + (uint32_t)buf * 512 + (uint32_t)tid * 16,
             (const char*)g_h + (size_t)kc * 512 + (size_t)tid * 16);
    CP_COMMIT();
}

__device__ __forceinline__ void buildA_fn(char* smem, const float* __restrict__ x,
                                          int n0, int tid) {
    const int row = tid >> 1;
    const int c0 = (tid & 1) * 8;
    const float4* xr = reinterpret_cast<const float4*>(x + (size_t)(n0 + row) * DD);
    uint4* As = reinterpret_cast<uint4*>(smem + OFF_A);
#pragma unroll
    for (int c = 0; c < 8; c++) {
        float4 p = xr[(c0 + c) * 2];
        float4 q = xr[(c0 + c) * 2 + 1];
        float v[8] = {p.x, p.y, p.z, p.w, q.x, q.y, q.z, q.w};
        uint4 H, M;
        uint32_t* hp = &H.x; uint32_t* mp = &M.x;
#pragma unroll
        for (int j = 0; j < 4; j++) {
            float v0 = v[2 * j], v1 = v[2 * j + 1];
            __half h0 = __float2half_rn(v0);
            __half h1 = __float2half_rn(v1);
            float r0 = v0 - __half2float(h0);
            float r1 = v1 - __half2float(h1);
            hp[j] = pk2h(v0, v1);
            mp[j] = pk2h(r0, r1);
        }
        int ci = row * 16 + ((c0 + c) ^ (row & 7));
        As[ci] = H;
        As[ci + 2048] = M;     // +32768 B
    }
}

// merge CTA-local bests and atomically publish for sample tile st_
__device__ __forceinline__ void flush_fn(char* smem, int st_, const float* best8,
                                         const int* idx8, int tid, int lane,
                                         int mwarp, int nwarp) {
    float* sbv = reinterpret_cast<float*>(smem);
    int*   siv = reinterpret_cast<int*>(smem + 2048);
    __syncthreads();
#pragma unroll
    for (int s = 0; s < 8; s++) {
        float v = best8[s];
        int ix = idx8[s];
#pragma unroll
        for (int off = 1; off < 4; off <<= 1) {
            float ov = __shfl_xor_sync(0xffffffffu, v, off);
            int   oi = __shfl_xor_sync(0xffffffffu, ix, off);
            if (ov > v || (ov == v && oi < ix)) { v = ov; ix = oi; }
        }
        if ((lane & 3) == 0) {
            int row = mwarp * 64 + (s >> 1) * 16 + (s & 1) * 8 + (lane >> 2);
            sbv[row * 4 + nwarp] = v;
            siv[row * 4 + nwarp] = ix;
        }
    }
    __syncthreads();
    if (tid < 128) {
        float bv = sbv[tid * 4];
        int bi = siv[tid * 4];
#pragma unroll
        for (int w = 1; w < 4; w++) {
            float v = sbv[tid * 4 + w];
            int ix = siv[tid * 4 + w];
            if (v > bv || (v == bv && ix < bi)) { bv = v; bi = ix; }
        }
        unsigned long long key = ((unsigned long long)enc_f(bv) << 32)
                               | (unsigned long long)(0xFFFFFFFFu - (unsigned)bi);
        atomicMax(&g_best[st_ * TM + tid], key);
    }
    __syncthreads();
}

// ---------------------------------------------------------------------------
// main: persistent 148 CTAs over 10112 (sample-tile, k-tile) units.
// 3-product fp16-split GEMM (hh + hm + mh) via mma.sync + running argmax.
// ---------------------------------------------------------------------------
__global__ void __launch_bounds__(256, 1)
vq_main(const float* __restrict__ x) {
    extern __shared__ __align__(1024) char smem[];
    const uint32_t sb = smem_u32(smem);
    const int tid = threadIdx.x;
    const int wid = tid >> 5;
    const int lane = tid & 31;
    const int l8 = lane & 7;
    const int g = lane >> 3;
    const int mwarp = wid >> 2;
    const int nwarp = wid & 3;
    const int bid = blockIdx.x;

    // contiguous unit range: first 48 CTAs get 69 units, rest 68
    const int start = bid * 68 + min(bid, 48);
    const int count = 68 + (bid < 48 ? 1 : 0);

    int cur_st = start / NT2;

    stageB_fn(sb, tid, start - cur_st * NT2, 0);
    buildA_fn(smem, x, cur_st * TM, tid);

    // per-lane address bases (XOR-fold swizzle)
    const uint32_t AQ  = sb + OFF_A + (uint32_t)mwarp * 16384u
                       + (uint32_t)l8 * 272 + ((uint32_t)(g & 1) << 11);
    const uint32_t gxa = (uint32_t)(g >> 1) << 4;
    const uint32_t gxb = (uint32_t)(g & 1) << 4;
    const uint32_t BQg = (uint32_t)nwarp * 8192u
                       + ((uint32_t)(g >> 1) << 11) + (uint32_t)l8 * 272;

    float best8[8];
    int   idx8[8];
#pragma unroll
    for (int i = 0; i < 8; i++) { best8[i] = -3.4e38f; idx8[i] = 0; }

    for (int i = 0; i < count; i++) {
        const int u = start + i;
        const int stt = u / NT2;
        const int kc = u - stt * NT2;
        const int b = i & 1;

        if (stt != cur_st) {   // block-uniform condition
            flush_fn(smem, cur_st, best8, idx8, tid, lane, mwarp, nwarp);
            buildA_fn(smem, x, stt * TM, tid);
            cur_st = stt;
#pragma unroll
            for (int s = 0; s < 8; s++) { best8[s] = -3.4e38f; idx8[s] = 0; }
        }

        if (i + 1 < count) {
            const int u2 = start + i + 1;
            stageB_fn(sb, tid, u2 - (u2 / NT2) * NT2, (i + 1) & 1);
            asm volatile("cp.async.wait_group 1;" ::: "memory");
        } else {
            asm volatile("cp.async.wait_group 0;" ::: "memory");
        }
        __syncthreads();

        // ---- compute tile kc on buffer b ----
        const uint32_t Bt = sb + OFF_B + (uint32_t)b * BUFB + BQg;
        float acc[4][4][4];
#pragma unroll
        for (int ma = 0; ma < 4; ma++)
#pragma unroll
            for (int nn = 0; nn < 4; nn++)
#pragma unroll
                for (int r = 0; r < 4; r++) acc[ma][nn][r] = 0.f;

#pragma unroll
        for (int ks = 0; ks < 8; ks++) {
            const uint32_t kxa = ((uint32_t)ks << 5) | gxa;
            const uint32_t kxb = ((uint32_t)ks << 5) | gxb;
            uint32_t a[2][4][4];
            uint32_t bf[2][2][4];
#pragma unroll
            for (int s = 0; s < 2; s++)
#pragma unroll
                for (int ma = 0; ma < 4; ma++)
                    LDSM4(a[s][ma],
                          (AQ + (uint32_t)s * 32768 + (uint32_t)ma * 4096) ^ kxa);
#pragma unroll
            for (int s = 0; s < 2; s++)
#pragma unroll
                for (int nb = 0; nb < 2; nb++)
                    LDSM4(bf[s][nb],
                          (Bt + (uint32_t)s * 32768 + (uint32_t)nb * 4096) ^ kxb);

            // 3 products: hh, hm, mh  (mm dropped: ~7e-7 abs, below fp32 noise)
            const int PA[3] = {0, 0, 1};
            const int PB[3] = {0, 1, 0};
#pragma unroll
            for (int p = 0; p < 3; p++)
#pragma unroll
                for (int ma = 0; ma < 4; ma++)
#pragma unroll
                    for (int nn = 0; nn < 4; nn++)
                        MMA(acc[ma][nn], a[PA[p]][ma],
                            bf[PB[p]][nn >> 1][2 * (nn & 1)],
                            bf[PB[p]][nn >> 1][2 * (nn & 1) + 1]);
        }

        // ---- running argmax on dist_rank = h_k - s.m_k ----
        const float* hb = reinterpret_cast<const float*>(smem + OFF_H + b * 512);
#pragma unroll
        for (int nn = 0; nn < 4; nn++) {
            const int hi0 = nwarp * 32 + nn * 8 + (lane & 3) * 2;
            const float h0 = hb[hi0];
            const float h1 = hb[hi0 + 1];
            const int c0 = kc * KT + hi0;
#pragma unroll
            for (int ma = 0; ma < 4; ma++) {
                float d0 = h0 - acc[ma][nn][0];
                float d1 = h1 - acc[ma][nn][1];
                float d2 = h0 - acc[ma][nn][2];
                float d3 = h1 - acc[ma][nn][3];
                const int s0 = ma * 2, s1 = ma * 2 + 1;
                if (d0 > best8[s0]) { best8[s0] = d0; idx8[s0] = c0; }
                if (d1 > best8[s0]) { best8[s0] = d1; idx8[s0] = c0 + 1; }
                if (d2 > best8[s1]) { best8[s1] = d2; idx8[s1] = c0; }
                if (d3 > best8[s1]) { best8[s1] = d3; idx8[s1] = c0 + 1; }
            }
        }
        __syncthreads();   // done reading buf b before it is overwritten
    }

    flush_fn(smem, cur_st, best8, idx8, tid, lane, mwarp, nwarp);
}

// ---------------------------------------------------------------------------
// decode g_best -> indices
// ---------------------------------------------------------------------------
__global__ void convert_kernel(float* __restrict__ out_idx_f) {
    int n = blockIdx.x * 256 + threadIdx.x;
    if (n >= NS) return;
    unsigned long long v = g_best[n];
    int ix = (int)(0xFFFFFFFFu - (unsigned)(v & 0xFFFFFFFFull));
    g_idx[n] = ix;
    out_idx_f[n] = (float)ix;
}

// ---------------------------------------------------------------------------
// gather quantize (coalesced via g_cmT) + partial MSE sums
// ---------------------------------------------------------------------------
__global__ void gather_kernel(const float* __restrict__ x,
                              float* __restrict__ out_q) {
    __shared__ float red[256];
    int tid = threadIdx.x;
    float local = 0.f;
    for (int e4 = blockIdx.x * blockDim.x + tid; e4 < NS * DD / 4;
         e4 += gridDim.x * blockDim.x) {
        int n = e4 >> 5;
        int d4 = (e4 & 31) * 4;
        float4 q = *reinterpret_cast<const float4*>(
            g_cmT + (size_t)g_idx[n] * DD + d4);
        float4 xv = reinterpret_cast<const float4*>(x)[e4];
        reinterpret_cast<float4*>(out_q)[e4] = q;
        float a = xv.x - q.x, bb = xv.y - q.y, c = xv.z - q.z, dd = xv.w - q.w;
        local = fmaf(a, a, local);
        local = fmaf(bb, bb, local);
        local = fmaf(c, c, local);
        local = fmaf(dd, dd, local);
    }
    red[tid] = local;
    __syncthreads();
    for (int s = 128; s; s >>= 1) {
        if (tid < s) red[tid] += red[tid + s];
        __syncthreads();
    }
    if (tid == 0) g_partial[blockIdx.x] = red[0];
}

__global__ void final_kernel(float* __restrict__ out) {
    __shared__ double red[256];
    int tid = threadIdx.x;
    double s = 0.0;
    for (int i = tid; i < 512; i += 256) s += (double)g_partial[i];
    red[tid] = s;
    __syncthreads();
    for (int st = 128; st; st >>= 1) {
        if (tid < st) red[tid] += red[tid + st];
        __syncthreads();
    }
    if (tid == 0)
        out[NS * DD + NS] = (float)(red[0] / (double)((size_t)NS * DD));
}

// ---------------------------------------------------------------------------
extern "C" void kernel_launch(void* const* d_in, const int* in_sizes, int n_in,
                              void* d_out, int out_size) {
    const float* x  = (const float*)d_in[0];   // [16384, 128]
    const float* cm = (const float*)d_in[1];   // [128, 10000]
    float* out = (float*)d_out;                // [quantize | index | diff]

    cudaFuncSetAttribute(vq_main,
                         cudaFuncAttributeMaxDynamicSharedMemorySize, SMEM_TOTAL);

    prepB_kernel<<<NT2 * 4, 256>>>(cm);
    vq_main<<<GRID, 256, SMEM_TOTAL>>>(x);
    convert_kernel<<<(NS + 255) / 256, 256>>>(out + (size_t)NS * DD);
    gather_kernel<<<512, 256>>>(x, out);
    final_kernel<<<1, 256>>>(out);
}